// round 14
// baseline (speedup 1.0000x reference)
#include <cuda_runtime.h>
#include <cuda_fp16.h>
#include <math.h>
#include <stdint.h>

// ============================================================================
// Problem constants
// ============================================================================
namespace {
constexpr int D = 512;
constexpr int L = 48;
constexpr int NPATCH = 8 * 7 * 24;     // 1344
constexpr int MTOT = NPATCH * L;       // 64512
constexpr int BM = 128, BN = 128;
constexpr int BK = 64;                 // fp16 elems per chunk
constexpr int NK0 = D / BK;            // 8 chunks
constexpr int NS = 3;                  // pipeline stages
constexpr int ROWB = 144;              // 128 data bytes + 16 pad (9 granules)
constexpr int ATILEB = 128 * ROWB;     // 18432
constexpr int STAGEB = 2 * ATILEB;     // 36864 (A + B)
constexpr int SMEM_DYN = NS * STAGEB;  // 110592  -> 2 CTAs/SM

constexpr int QBLKS = (int)((size_t)MTOT * D / 4 / 256);  // 32256
constexpr int WBLKS = (D * D / 4) / 256;                  // 256

// attention smem layout (bytes)
constexpr int QROWB = 272;             // 128 fp16 data + 16B pad (17 granules)
constexpr int QS_B = 64 * QROWB;       // (rows 48-63 unused)
constexpr int KS_B = 48 * QROWB;
constexpr int VS_B = 48 * QROWB;
constexpr int SF_B = 48 * 49 * 4;
constexpr int P_ROWB = 112;            // 48 fp16 + 16B pad (7 granules)
constexpr int PH_B = 48 * P_ROWB;
constexpr int QS_OFF = 0;
constexpr int KS_OFF = QS_OFF + QS_B;
constexpr int VS_OFF = KS_OFF + KS_B;
constexpr int SF_OFF = VS_OFF + VS_B;
constexpr int PH_OFF = SF_OFF + SF_B;
constexpr int PL_OFF = PH_OFF + PH_B;
constexpr int ATTN_SMEM = PL_OFF + PH_B;   // 63680
}

// ============================================================================
// Scratch (__device__ globals; no cudaMalloc allowed)
// ============================================================================
__device__ __half g_xq[(size_t)MTOT * D];   // inputs rounded to fp16
__device__ __half g_xk[(size_t)MTOT * D];
__device__ __half g_xv[(size_t)MTOT * D];
__device__ __half g_q[(size_t)MTOT * D];    // projections (fp16)
__device__ __half g_k[(size_t)MTOT * D];
__device__ __half g_v[(size_t)MTOT * D];
__device__ __half g_xo[(size_t)MTOT * D];   // attention out, fp16
__device__ __half g_wq[D * D];              // weights rounded to fp16
__device__ __half g_wk[D * D];
__device__ __half g_wo[D * D];

// ============================================================================
// PTX helpers (sm_90-compatible baseline PTX only — NO tcgen05; harness
// compiles PTX for compute_103 without the 'a' suffix)
// ============================================================================
__device__ __forceinline__ uint32_t smem_u32(const void* p) {
    uint32_t a;
    asm("{ .reg .u64 t; cvta.to.shared.u64 t, %1; cvt.u32.u64 %0, t; }"
        : "=r"(a) : "l"(p));
    return a;
}
__device__ __forceinline__ void cp_async16(uint32_t dst, const void* src) {
    asm volatile("cp.async.cg.shared.global [%0], [%1], 16;" :: "r"(dst), "l"(src));
}
__device__ __forceinline__ void cp_commit() {
    asm volatile("cp.async.commit_group;" ::: "memory");
}
template <int N>
__device__ __forceinline__ void cp_wait() {
    asm volatile("cp.async.wait_group %0;" :: "n"(N) : "memory");
}
__device__ __forceinline__ void ldsm4(uint32_t* r, uint32_t addr) {
    asm volatile("ldmatrix.sync.aligned.m8n8.x4.shared.b16 {%0,%1,%2,%3}, [%4];"
                 : "=r"(r[0]), "=r"(r[1]), "=r"(r[2]), "=r"(r[3]) : "r"(addr));
}
__device__ __forceinline__ void ldsm4t(uint32_t* r, uint32_t addr) {
    asm volatile("ldmatrix.sync.aligned.m8n8.x4.trans.shared.b16 {%0,%1,%2,%3}, [%4];"
                 : "=r"(r[0]), "=r"(r[1]), "=r"(r[2]), "=r"(r[3]) : "r"(addr));
}
__device__ __forceinline__ void mma16816(float* c, const uint32_t* a,
                                         const uint32_t* b) {
    asm volatile(
        "mma.sync.aligned.m16n8k16.row.col.f32.f16.f16.f32 "
        "{%0,%1,%2,%3}, {%4,%5,%6,%7}, {%8,%9}, {%0,%1,%2,%3};"
        : "+f"(c[0]), "+f"(c[1]), "+f"(c[2]), "+f"(c[3])
        : "r"(a[0]), "r"(a[1]), "r"(a[2]), "r"(a[3]), "r"(b[0]), "r"(b[1]));
}

// ============================================================================
// conversions
// ============================================================================
__device__ __forceinline__ ushort4 to_h4(const float4 a) {
    ushort4 r;
    r.x = __half_as_ushort(__float2half(a.x));
    r.y = __half_as_ushort(__float2half(a.y));
    r.z = __half_as_ushort(__float2half(a.z));
    r.w = __half_as_ushort(__float2half(a.w));
    return r;
}

// q conversion + weight conversion folded into one launch (extra blocks)
__global__ __launch_bounds__(256) void conv_q_w(
    const float* __restrict__ q, const float* __restrict__ wq,
    const float* __restrict__ wkv, const float* __restrict__ wo)
{
    int b = blockIdx.x;
    if (b < QBLKS) {
        size_t i4 = (size_t)b * 256 + threadIdx.x;
        *(ushort4*)(g_xq + i4 * 4) = to_h4(((const float4*)q)[i4]);
    } else {
        size_t i4 = (size_t)(b - QBLKS) * 256 + threadIdx.x;
        size_t idx = i4 * 4;
        *(ushort4*)(g_wq + idx) = to_h4(((const float4*)wq)[i4]);
        *(ushort4*)(g_wk + idx) = to_h4(((const float4*)wkv)[i4]);
        *(ushort4*)(g_wo + idx) = to_h4(((const float4*)wo)[i4]);
    }
}

__global__ __launch_bounds__(256) void conv_k(const float* __restrict__ k)
{
    size_t i4 = (size_t)blockIdx.x * 256 + threadIdx.x;
    *(ushort4*)(g_xk + i4 * 4) = to_h4(((const float4*)k)[i4]);
}

__global__ __launch_bounds__(256) void conv_v(const float* __restrict__ v)
{
    size_t i4 = (size_t)blockIdx.x * 256 + threadIdx.x;
    *(ushort4*)(g_xv + i4 * 4) = to_h4(((const float4*)v)[i4]);
}

// ============================================================================
// HMMA GEMM (fp16 1-term): C[m][n] = sum_d A[m][d]*W[n][d] + bias[n]
// BM=128 x BN=128 x BK=64, 256 threads (2x4 warp grid, 64x32 per warp),
// NS=3 pipeline, ONE __syncthreads per chunk, 2 CTAs/SM.   (round-9 proven)
// ============================================================================
template <bool WriteHalf>
__device__ __forceinline__ void gemm_body(
    const __half* __restrict__ A, const __half* __restrict__ B,
    const float* __restrict__ bias, float* __restrict__ Cf,
    __half* __restrict__ Ch)
{
    extern __shared__ __align__(16) char dsm[];
    const uint32_t smem = smem_u32(dsm);
    __shared__ float bias_s[BN];

    const int tid = threadIdx.x;
    const int wid = tid >> 5, lane = tid & 31;
    const int wm = wid & 1, wn = wid >> 1;           // 2 x 4 warp grid
    const int n0 = blockIdx.x * BN;
    const int m0 = blockIdx.y * BM;

    if (tid < BN) bias_s[tid] = bias[n0 + tid];

    float acc[4][4][4];
#pragma unroll
    for (int i = 0; i < 4; i++)
#pragma unroll
        for (int j = 0; j < 4; j++)
#pragma unroll
            for (int e = 0; e < 4; e++) acc[i][j][e] = 0.0f;

    auto load_chunk = [&](int c) {
        const int s = c % NS;
        const int k0 = c * BK;
        const uint32_t st = smem + (uint32_t)s * STAGEB;
#pragma unroll
        for (int r = 0; r < 4; r++) {
            int id = tid + r * 256;          // 0..1023
            int row = id >> 3, g = id & 7;
            cp_async16(st + row * ROWB + g * 16,
                       A + (size_t)(m0 + row) * D + k0 + g * 8);
            cp_async16(st + ATILEB + row * ROWB + g * 16,
                       B + (size_t)(n0 + row) * D + k0 + g * 8);
        }
        cp_commit();
    };

    load_chunk(0);
    load_chunk(1);

    const uint32_t aLaneRow = (uint32_t)(wm * 64 + (lane & 15));
    const uint32_t aLaneOff = (uint32_t)(((lane >> 4) & 1) * 16);
    const uint32_t bLaneRow = (uint32_t)(wn * 32 + ((lane >> 4) & 1) * 8 + (lane & 7));
    const uint32_t bLaneOff = (uint32_t)(((lane >> 3) & 1) * 16);

    for (int c = 0; c < NK0; c++) {
        if (c == NK0 - 1) cp_wait<0>();
        else cp_wait<1>();
        __syncthreads();                     // all warps done reading buf (c-1)%NS
        if (c + NS - 1 < NK0) load_chunk(c + NS - 1);   // writes buf (c-1)%NS

        const int s = c % NS;
        const uint32_t st = smem + (uint32_t)s * STAGEB;
        const uint32_t aAddr = st + aLaneRow * ROWB + aLaneOff;
        const uint32_t bAddr = st + ATILEB + bLaneRow * ROWB + bLaneOff;

#pragma unroll
        for (int ks = 0; ks < 4; ks++) {
            uint32_t a[4][4], b[2][4];
#pragma unroll
            for (int mf = 0; mf < 4; mf++)
                ldsm4(a[mf], aAddr + mf * 16 * ROWB + ks * 32);
#pragma unroll
            for (int bp = 0; bp < 2; bp++)
                ldsm4(b[bp], bAddr + bp * 16 * ROWB + ks * 32);
#pragma unroll
            for (int mf = 0; mf < 4; mf++)
#pragma unroll
                for (int nf = 0; nf < 4; nf++)
                    mma16816(acc[mf][nf], a[mf], &b[nf >> 1][(nf & 1) * 2]);
        }
    }

    // Epilogue
    const int gr = lane >> 2, tc = lane & 3;
#pragma unroll
    for (int mf = 0; mf < 4; mf++) {
#pragma unroll
        for (int nf = 0; nf < 4; nf++) {
            int rowo = m0 + wm * 64 + mf * 16 + gr;
            int coll = wn * 32 + nf * 8 + tc * 2;
            int col = n0 + coll;
            float b0 = bias_s[coll], b1 = bias_s[coll + 1];
            float v0 = acc[mf][nf][0] + b0, v1 = acc[mf][nf][1] + b1;
            float v2 = acc[mf][nf][2] + b0, v3 = acc[mf][nf][3] + b1;
            if (WriteHalf) {
                __half2 p0; p0.x = __float2half(v0); p0.y = __float2half(v1);
                __half2 p1; p1.x = __float2half(v2); p1.y = __float2half(v3);
                *(__half2*)(Ch + (size_t)rowo * D + col) = p0;
                *(__half2*)(Ch + (size_t)(rowo + 8) * D + col) = p1;
            } else {
                float2 p0; p0.x = v0; p0.y = v1;
                float2 p1; p1.x = v2; p1.y = v3;
                *(float2*)(Cf + (size_t)rowo * D + col) = p0;
                *(float2*)(Cf + (size_t)(rowo + 8) * D + col) = p1;
            }
        }
    }
}

__global__ __launch_bounds__(256, 2) void gemm_proj(int z,
                                                    const float* __restrict__ bias)
{
    const __half* A = (z == 0) ? g_xq : (z == 1) ? g_xk : g_xv;
    const __half* B = (z == 0) ? g_wq : g_wk;
    __half* C = (z == 0) ? g_q : (z == 1) ? g_k : g_v;
    gemm_body<true>(A, B, bias, nullptr, C);
}

__global__ __launch_bounds__(256, 2) void gemm_out(const float* __restrict__ bo,
                                                   float* __restrict__ out)
{
    gemm_body<false>(g_xo, g_wo, bo, out, nullptr);
}

// ============================================================================
// HMMA fused per-patch attention (round-13 proven; unchanged).
// ============================================================================
__global__ __launch_bounds__(256) void attn_kernel()
{
    extern __shared__ __align__(16) char smraw[];
    const uint32_t sm = smem_u32(smraw);
    const uint32_t qs = sm + QS_OFF, ks = sm + KS_OFF, vs = sm + VS_OFF;
    float* Sf = (float*)(smraw + SF_OFF);
    __half* Phc = (__half*)(smraw + PH_OFF);
    __half* Plc = (__half*)(smraw + PL_OFF);
    const uint32_t phA = sm + PH_OFF, plA = sm + PL_OFF;

    const int patch = blockIdx.x;
    const size_t base = (size_t)patch * L * D;
    const int tid = threadIdx.x;
    const int wid = tid >> 5, lane = tid & 31;
    const int mb = wid & 3;
    const int gr = lane >> 2, tc = lane & 3;

    const uint32_t aRowOff = (uint32_t)(mb * 16 + (lane & 15)) * QROWB;
    const uint32_t aOff = (uint32_t)(((lane >> 4) & 1) * 16);
    const uint32_t bRowBase = (uint32_t)(((lane >> 4) & 1) * 8 + (lane & 7));
    const uint32_t bOff = (uint32_t)(((lane >> 3) & 1) * 16);
    const int ng0 = (wid < 4) ? 0 : 1;
    const int ntiles = (wid < 4) ? 2 : 1;

    float accS[2][2][4];
#pragma unroll
    for (int t = 0; t < 2; t++)
#pragma unroll
        for (int j = 0; j < 2; j++)
#pragma unroll
            for (int e = 0; e < 4; e++) accS[t][j][e] = 0.0f;

    auto load_half = [&](int h) {
        const uint32_t p = (uint32_t)(h & 1) * 128;
        const int d0 = h * 64;
#pragma unroll
        for (int r = 0; r < 3; r++) {
            int id = tid + r * 256;          // 0..767
            int isK = id >= 384;
            int li = isK ? id - 384 : id;    // 0..383
            int rw = li >> 3, g = li & 7;
            uint32_t dst = (isK ? ks : qs) + rw * QROWB + p + g * 16;
            const __half* src = (isK ? g_k : g_q) + base + (size_t)rw * D + d0 + g * 8;
            cp_async16(dst, src);
        }
        cp_commit();
    };

    // ---- Stage 1: S = q k^T, 8 half-chunks of 64 cols, double-buffered ----
    load_half(0);
    for (int h = 0; h < 8; h++) {
        cp_wait<0>();
        __syncthreads();
        if (h + 1 < 8) load_half(h + 1);

        const uint32_t p = (uint32_t)(h & 1) * 128;
#pragma unroll
        for (int kk = 0; kk < 4; kk++) {
            uint32_t a[4];
            ldsm4(a, qs + aRowOff + p + kk * 32 + aOff);
#pragma unroll
            for (int t = 0; t < 2; t++) {
                if (t >= ntiles) break;
                int ng = ng0 + t * 2;
                uint32_t b[4];
                ldsm4(b, ks + (uint32_t)(ng * 16) * QROWB + bRowBase * QROWB + p + kk * 32 + bOff);
                mma16816(accS[t][0], a, &b[0]);
                mma16816(accS[t][1], a, &b[2]);
            }
        }
        __syncthreads();
    }

    // Prefetch v chunk 0 into vs — completes under S-store/softmax/P-convert.
#pragma unroll
    for (int r = 0; r < 3; r++) {
        int id = tid + r * 256;
        int rw = id >> 4, g = id & 15;
        cp_async16(vs + rw * QROWB + g * 16, g_v + base + (size_t)rw * D + g * 8);
    }
    cp_commit();

    // store S (band 3 discarded)
    if (mb < 3) {
#pragma unroll
        for (int t = 0; t < 2; t++) {
            if (t >= ntiles) break;
            int ng = ng0 + t * 2;
#pragma unroll
            for (int j = 0; j < 2; j++) {
                int col = ng * 16 + j * 8 + tc * 2;
                Sf[(mb * 16 + gr) * 49 + col]         = accS[t][j][0];
                Sf[(mb * 16 + gr) * 49 + col + 1]     = accS[t][j][1];
                Sf[(mb * 16 + gr + 8) * 49 + col]     = accS[t][j][2];
                Sf[(mb * 16 + gr + 8) * 49 + col + 1] = accS[t][j][3];
            }
        }
    }
    __syncthreads();

    // ---- Stage 2: softmax with diag mask ----
    if (tid < 48) {
        const float scale = 0.044194173824159216f;   // 512^-0.5
        float m = -INFINITY;
#pragma unroll
        for (int c = 0; c < 48; c++)
            if (c != tid) m = fmaxf(m, Sf[tid * 49 + c] * scale);
        float sum = 0.0f;
#pragma unroll
        for (int c = 0; c < 48; c++) {
            float e = (c == tid) ? 0.0f : __expf(Sf[tid * 49 + c] * scale - m);
            Sf[tid * 49 + c] = e;
            sum += e;
        }
        float inv = 1.0f / sum;
#pragma unroll
        for (int c = 0; c < 48; c++) Sf[tid * 49 + c] *= inv;
    }
    __syncthreads();

    // convert P to fp16 hi/lo (A-operand layout, 112B rows)
    for (int idx = tid; idx < 48 * 48; idx += 256) {
        int r = idx / 48, c = idx - r * 48;
        float p = Sf[r * 49 + c];
        __half hh = __float2half(p);
        Phc[r * (P_ROWB / 2) + c] = hh;
        Plc[r * (P_ROWB / 2) + c] = __float2half(p - __half2float(hh));
    }

    // ---- Stage 3: out = P @ v, 4 chunks of 128 d-cols, ping-pong vs/qs ----
    const int qd = lane >> 3;
    const uint32_t vRow = (uint32_t)((qd & 1) * 8 + (lane & 7));
    const uint32_t vCol = (uint32_t)(wid * 32 + (qd >> 1) * 16);
    const uint32_t pRow = (uint32_t)(lane & 15);

    for (int cc = 0; cc < 4; cc++) {
        const int d0 = cc * 128;
        cp_wait<0>();
        __syncthreads();
        if (cc + 1 < 4) {
            const uint32_t nb = ((cc + 1) & 1) ? qs : vs;
            const int nd0 = (cc + 1) * 128;
#pragma unroll
            for (int r = 0; r < 3; r++) {
                int id = tid + r * 256;
                int rw = id >> 4, g = id & 15;
                cp_async16(nb + rw * QROWB + g * 16,
                           g_v + base + (size_t)rw * D + nd0 + g * 8);
            }
            cp_commit();
        }
        const uint32_t vb = (cc & 1) ? qs : vs;

        float acc[3][2][4];
#pragma unroll
        for (int i = 0; i < 3; i++)
#pragma unroll
            for (int j = 0; j < 2; j++)
#pragma unroll
                for (int e = 0; e < 4; e++) acc[i][j][e] = 0.0f;

#pragma unroll
        for (int kk = 0; kk < 3; kk++) {
            uint32_t b[4];
            ldsm4t(b, vb + (uint32_t)(kk * 16 + vRow) * QROWB + vCol);
#pragma unroll
            for (int mbb = 0; mbb < 3; mbb++) {
                uint32_t ah[4], al[4];
                ldsm4(ah, phA + (uint32_t)(mbb * 16 + pRow) * P_ROWB + kk * 32 + aOff);
                ldsm4(al, plA + (uint32_t)(mbb * 16 + pRow) * P_ROWB + kk * 32 + aOff);
                mma16816(acc[mbb][0], ah, &b[0]);
                mma16816(acc[mbb][1], ah, &b[2]);
                mma16816(acc[mbb][0], al, &b[0]);
                mma16816(acc[mbb][1], al, &b[2]);
            }
        }

#pragma unroll
        for (int mbb = 0; mbb < 3; mbb++)
#pragma unroll
            for (int j = 0; j < 2; j++) {
                int row = mbb * 16 + gr;
                int col = d0 + wid * 16 + j * 8 + tc * 2;
                __half2 p0, p1;
                p0.x = __float2half(acc[mbb][j][0]);
                p0.y = __float2half(acc[mbb][j][1]);
                p1.x = __float2half(acc[mbb][j][2]);
                p1.y = __float2half(acc[mbb][j][3]);
                *(__half2*)(g_xo + base + (size_t)row * D + col) = p0;
                *(__half2*)(g_xo + base + (size_t)(row + 8) * D + col) = p1;
            }
        __syncthreads();
    }
}

// ============================================================================
// Launch: fork-join stream graph so conv_k / conv_v overlap the GEMMs.
//   stream 0 : conv_q_w -> gemm_q ........ (wait k,v) -> attn -> gemm_out
//   s1 (fork): conv_k -> gemm_k
//   s2       : (after conv_k) conv_v -> gemm_v
// ============================================================================
extern "C" void kernel_launch(void* const* d_in, const int* in_sizes, int n_in,
                              void* d_out, int out_size)
{
    const float* queries = (const float*)d_in[0];
    const float* keys    = (const float*)d_in[1];
    const float* values  = (const float*)d_in[2];
    const float* Wq      = (const float*)d_in[3];
    const float* bq      = (const float*)d_in[4];
    const float* Wkv     = (const float*)d_in[5];
    const float* bkv     = (const float*)d_in[6];
    const float* Wo      = (const float*)d_in[7];
    const float* bo      = (const float*)d_in[8];
    float* out = (float*)d_out;

    static cudaStream_t s1 = nullptr, s2 = nullptr;
    static cudaEvent_t eFork, eK, eKd, eVd;
    if (s1 == nullptr) {
        cudaStreamCreateWithFlags(&s1, cudaStreamNonBlocking);
        cudaStreamCreateWithFlags(&s2, cudaStreamNonBlocking);
        cudaEventCreateWithFlags(&eFork, cudaEventDisableTiming);
        cudaEventCreateWithFlags(&eK, cudaEventDisableTiming);
        cudaEventCreateWithFlags(&eKd, cudaEventDisableTiming);
        cudaEventCreateWithFlags(&eVd, cudaEventDisableTiming);
    }

    cudaFuncSetAttribute(gemm_proj, cudaFuncAttributeMaxDynamicSharedMemorySize,
                         SMEM_DYN);
    cudaFuncSetAttribute(gemm_out, cudaFuncAttributeMaxDynamicSharedMemorySize,
                         SMEM_DYN);
    cudaFuncSetAttribute(attn_kernel, cudaFuncAttributeMaxDynamicSharedMemorySize,
                         ATTN_SMEM);

    const dim3 gproj(D / BN, MTOT / BM);

    // stream 0: weights + q conversion, then fork
    conv_q_w<<<QBLKS + WBLKS, 256>>>(queries, Wq, Wkv, Wo);
    cudaEventRecord(eFork, 0);

    // branch 1: k
    cudaStreamWaitEvent(s1, eFork, 0);
    conv_k<<<QBLKS, 256, 0, s1>>>(keys);
    cudaEventRecord(eK, s1);
    gemm_proj<<<gproj, 256, SMEM_DYN, s1>>>(1, bkv);
    cudaEventRecord(eKd, s1);

    // branch 2: v (conversion starts after conv_k to avoid BW contention)
    cudaStreamWaitEvent(s2, eK, 0);
    conv_v<<<QBLKS, 256, 0, s2>>>(values);
    gemm_proj<<<gproj, 256, SMEM_DYN, s2>>>(2, bkv);
    cudaEventRecord(eVd, s2);

    // stream 0: q GEMM overlaps the k/v conversions
    gemm_proj<<<gproj, 256, SMEM_DYN>>>(0, bq);

    // join and finish
    cudaStreamWaitEvent(0, eKd, 0);
    cudaStreamWaitEvent(0, eVd, 0);
    attn_kernel<<<NPATCH, 256, ATTN_SMEM>>>();
    gemm_out<<<gproj, 256, SMEM_DYN>>>(bo, out);
}

// round 15
// speedup vs baseline: 1.0223x; 1.0223x over previous
#include <cuda_runtime.h>
#include <cuda_fp16.h>
#include <math.h>
#include <stdint.h>

// ============================================================================
// Problem constants
// ============================================================================
namespace {
constexpr int D = 512;
constexpr int L = 48;
constexpr int NPATCH = 8 * 7 * 24;     // 1344
constexpr int MTOT = NPATCH * L;       // 64512
constexpr int BM = 128, BN = 128;
constexpr int BK = 64;                 // fp16 elems per chunk
constexpr int NK0 = D / BK;            // 8 chunks
constexpr int NS = 3;                  // pipeline stages
constexpr int ROWB = 144;              // 128 data bytes + 16 pad (9 granules)
constexpr int ATILEB = 128 * ROWB;     // 18432
constexpr int STAGEB = 2 * ATILEB;     // 36864 (A + B)
constexpr int SMEM_DYN = NS * STAGEB;  // 110592  -> 2 CTAs/SM

// attention smem layout (bytes)
constexpr int QROWB = 272;             // 128 fp16 data + 16B pad (17 granules)
constexpr int QS_B = 64 * QROWB;       // (rows 48-63 unused)
constexpr int KS_B = 48 * QROWB;
constexpr int VS_B = 48 * QROWB;
constexpr int SF_B = 48 * 49 * 4;
constexpr int P_ROWB = 112;            // 48 fp16 + 16B pad (7 granules)
constexpr int PH_B = 48 * P_ROWB;
constexpr int QS_OFF = 0;
constexpr int KS_OFF = QS_OFF + QS_B;
constexpr int VS_OFF = KS_OFF + KS_B;
constexpr int SF_OFF = VS_OFF + VS_B;
constexpr int PH_OFF = SF_OFF + SF_B;
constexpr int PL_OFF = PH_OFF + PH_B;
constexpr int ATTN_SMEM = PL_OFF + PH_B;   // 63680
}

// ============================================================================
// Scratch (__device__ globals; no cudaMalloc allowed)
// ============================================================================
__device__ __half g_xq[(size_t)MTOT * D];   // inputs rounded to fp16
__device__ __half g_xk[(size_t)MTOT * D];
__device__ __half g_xv[(size_t)MTOT * D];
__device__ __half g_q[(size_t)MTOT * D];    // projections (fp16)
__device__ __half g_k[(size_t)MTOT * D];
__device__ __half g_v[(size_t)MTOT * D];
__device__ __half g_xo[(size_t)MTOT * D];   // attention out, fp16
__device__ __half g_wq[D * D];              // weights rounded to fp16
__device__ __half g_wk[D * D];
__device__ __half g_wo[D * D];

// ============================================================================
// PTX helpers (sm_90-compatible baseline PTX only — NO tcgen05; harness
// compiles PTX for compute_103 without the 'a' suffix)
// ============================================================================
__device__ __forceinline__ uint32_t smem_u32(const void* p) {
    uint32_t a;
    asm("{ .reg .u64 t; cvta.to.shared.u64 t, %1; cvt.u32.u64 %0, t; }"
        : "=r"(a) : "l"(p));
    return a;
}
__device__ __forceinline__ void cp_async16(uint32_t dst, const void* src) {
    asm volatile("cp.async.cg.shared.global [%0], [%1], 16;" :: "r"(dst), "l"(src));
}
__device__ __forceinline__ void cp_commit() {
    asm volatile("cp.async.commit_group;" ::: "memory");
}
template <int N>
__device__ __forceinline__ void cp_wait() {
    asm volatile("cp.async.wait_group %0;" :: "n"(N) : "memory");
}
__device__ __forceinline__ void ldsm4(uint32_t* r, uint32_t addr) {
    asm volatile("ldmatrix.sync.aligned.m8n8.x4.shared.b16 {%0,%1,%2,%3}, [%4];"
                 : "=r"(r[0]), "=r"(r[1]), "=r"(r[2]), "=r"(r[3]) : "r"(addr));
}
__device__ __forceinline__ void ldsm4t(uint32_t* r, uint32_t addr) {
    asm volatile("ldmatrix.sync.aligned.m8n8.x4.trans.shared.b16 {%0,%1,%2,%3}, [%4];"
                 : "=r"(r[0]), "=r"(r[1]), "=r"(r[2]), "=r"(r[3]) : "r"(addr));
}
__device__ __forceinline__ void mma16816(float* c, const uint32_t* a,
                                         const uint32_t* b) {
    asm volatile(
        "mma.sync.aligned.m16n8k16.row.col.f32.f16.f16.f32 "
        "{%0,%1,%2,%3}, {%4,%5,%6,%7}, {%8,%9}, {%0,%1,%2,%3};"
        : "+f"(c[0]), "+f"(c[1]), "+f"(c[2]), "+f"(c[3])
        : "r"(a[0]), "r"(a[1]), "r"(a[2]), "r"(a[3]), "r"(b[0]), "r"(b[1]));
}

// ============================================================================
// conversions
// ============================================================================
__device__ __forceinline__ uint32_t pack_h2(float a, float b) {
    __half2 h = __floats2half2_rn(a, b);
    return *(uint32_t*)&h;
}

// 2 x float4 -> 1 x 16B fp16 store per tensor per thread
__global__ __launch_bounds__(256) void conv_inputs(
    const float* __restrict__ q, const float* __restrict__ k,
    const float* __restrict__ v)
{
    size_t i8 = (size_t)blockIdx.x * 256 + threadIdx.x;
    size_t f4 = i8 * 2;
    size_t idx = i8 * 8;
    {
        float4 a0 = ((const float4*)q)[f4];
        float4 a1 = ((const float4*)q)[f4 + 1];
        uint4 p = make_uint4(pack_h2(a0.x, a0.y), pack_h2(a0.z, a0.w),
                             pack_h2(a1.x, a1.y), pack_h2(a1.z, a1.w));
        *(uint4*)(g_xq + idx) = p;
    }
    {
        float4 a0 = ((const float4*)k)[f4];
        float4 a1 = ((const float4*)k)[f4 + 1];
        uint4 p = make_uint4(pack_h2(a0.x, a0.y), pack_h2(a0.z, a0.w),
                             pack_h2(a1.x, a1.y), pack_h2(a1.z, a1.w));
        *(uint4*)(g_xk + idx) = p;
    }
    {
        float4 a0 = ((const float4*)v)[f4];
        float4 a1 = ((const float4*)v)[f4 + 1];
        uint4 p = make_uint4(pack_h2(a0.x, a0.y), pack_h2(a0.z, a0.w),
                             pack_h2(a1.x, a1.y), pack_h2(a1.z, a1.w));
        *(uint4*)(g_xv + idx) = p;
    }
}

__global__ __launch_bounds__(256) void conv_weights(
    const float* __restrict__ wq, const float* __restrict__ wkv,
    const float* __restrict__ wo)
{
    size_t i8 = (size_t)blockIdx.x * 256 + threadIdx.x;
    size_t f4 = i8 * 2;
    size_t idx = i8 * 8;
    {
        float4 a0 = ((const float4*)wq)[f4];
        float4 a1 = ((const float4*)wq)[f4 + 1];
        *(uint4*)(g_wq + idx) = make_uint4(pack_h2(a0.x, a0.y), pack_h2(a0.z, a0.w),
                                           pack_h2(a1.x, a1.y), pack_h2(a1.z, a1.w));
    }
    {
        float4 a0 = ((const float4*)wkv)[f4];
        float4 a1 = ((const float4*)wkv)[f4 + 1];
        *(uint4*)(g_wk + idx) = make_uint4(pack_h2(a0.x, a0.y), pack_h2(a0.z, a0.w),
                                           pack_h2(a1.x, a1.y), pack_h2(a1.z, a1.w));
    }
    {
        float4 a0 = ((const float4*)wo)[f4];
        float4 a1 = ((const float4*)wo)[f4 + 1];
        *(uint4*)(g_wo + idx) = make_uint4(pack_h2(a0.x, a0.y), pack_h2(a0.z, a0.w),
                                           pack_h2(a1.x, a1.y), pack_h2(a1.z, a1.w));
    }
}

// ============================================================================
// HMMA GEMM (fp16 1-term): C[m][n] = sum_d A[m][d]*W[n][d] + bias[n]
// BM=128 x BN=128 x BK=64, 256 threads (2x4 warp grid, 64x32 per warp),
// NS=3 pipeline, ONE __syncthreads per chunk, 2 CTAs/SM.   (round-9 proven)
// ============================================================================
template <bool WriteHalf>
__device__ __forceinline__ void gemm_body(
    const __half* __restrict__ A, const __half* __restrict__ B,
    const float* __restrict__ bias, float* __restrict__ Cf,
    __half* __restrict__ Ch)
{
    extern __shared__ __align__(16) char dsm[];
    const uint32_t smem = smem_u32(dsm);
    __shared__ float bias_s[BN];

    const int tid = threadIdx.x;
    const int wid = tid >> 5, lane = tid & 31;
    const int wm = wid & 1, wn = wid >> 1;           // 2 x 4 warp grid
    const int n0 = blockIdx.x * BN;
    const int m0 = blockIdx.y * BM;

    if (tid < BN) bias_s[tid] = bias[n0 + tid];

    float acc[4][4][4];
#pragma unroll
    for (int i = 0; i < 4; i++)
#pragma unroll
        for (int j = 0; j < 4; j++)
#pragma unroll
            for (int e = 0; e < 4; e++) acc[i][j][e] = 0.0f;

    auto load_chunk = [&](int c) {
        const int s = c % NS;
        const int k0 = c * BK;
        const uint32_t st = smem + (uint32_t)s * STAGEB;
#pragma unroll
        for (int r = 0; r < 4; r++) {
            int id = tid + r * 256;          // 0..1023
            int row = id >> 3, g = id & 7;
            cp_async16(st + row * ROWB + g * 16,
                       A + (size_t)(m0 + row) * D + k0 + g * 8);
            cp_async16(st + ATILEB + row * ROWB + g * 16,
                       B + (size_t)(n0 + row) * D + k0 + g * 8);
        }
        cp_commit();
    };

    load_chunk(0);
    load_chunk(1);

    const uint32_t aLaneRow = (uint32_t)(wm * 64 + (lane & 15));
    const uint32_t aLaneOff = (uint32_t)(((lane >> 4) & 1) * 16);
    const uint32_t bLaneRow = (uint32_t)(wn * 32 + ((lane >> 4) & 1) * 8 + (lane & 7));
    const uint32_t bLaneOff = (uint32_t)(((lane >> 3) & 1) * 16);

    for (int c = 0; c < NK0; c++) {
        if (c == NK0 - 1) cp_wait<0>();
        else cp_wait<1>();
        __syncthreads();                     // all warps done reading buf (c-1)%NS
        if (c + NS - 1 < NK0) load_chunk(c + NS - 1);   // writes buf (c-1)%NS

        const int s = c % NS;
        const uint32_t st = smem + (uint32_t)s * STAGEB;
        const uint32_t aAddr = st + aLaneRow * ROWB + aLaneOff;
        const uint32_t bAddr = st + ATILEB + bLaneRow * ROWB + bLaneOff;

#pragma unroll
        for (int ks = 0; ks < 4; ks++) {
            uint32_t a[4][4], b[2][4];
#pragma unroll
            for (int mf = 0; mf < 4; mf++)
                ldsm4(a[mf], aAddr + mf * 16 * ROWB + ks * 32);
#pragma unroll
            for (int bp = 0; bp < 2; bp++)
                ldsm4(b[bp], bAddr + bp * 16 * ROWB + ks * 32);
#pragma unroll
            for (int mf = 0; mf < 4; mf++)
#pragma unroll
                for (int nf = 0; nf < 4; nf++)
                    mma16816(acc[mf][nf], a[mf], &b[nf >> 1][(nf & 1) * 2]);
        }
    }

    // Epilogue
    const int gr = lane >> 2, tc = lane & 3;
#pragma unroll
    for (int mf = 0; mf < 4; mf++) {
#pragma unroll
        for (int nf = 0; nf < 4; nf++) {
            int rowo = m0 + wm * 64 + mf * 16 + gr;
            int coll = wn * 32 + nf * 8 + tc * 2;
            int col = n0 + coll;
            float b0 = bias_s[coll], b1 = bias_s[coll + 1];
            float v0 = acc[mf][nf][0] + b0, v1 = acc[mf][nf][1] + b1;
            float v2 = acc[mf][nf][2] + b0, v3 = acc[mf][nf][3] + b1;
            if (WriteHalf) {
                __half2 p0; p0.x = __float2half(v0); p0.y = __float2half(v1);
                __half2 p1; p1.x = __float2half(v2); p1.y = __float2half(v3);
                *(__half2*)(Ch + (size_t)rowo * D + col) = p0;
                *(__half2*)(Ch + (size_t)(rowo + 8) * D + col) = p1;
            } else {
                float2 p0; p0.x = v0; p0.y = v1;
                float2 p1; p1.x = v2; p1.y = v3;
                *(float2*)(Cf + (size_t)rowo * D + col) = p0;
                *(float2*)(Cf + (size_t)(rowo + 8) * D + col) = p1;
            }
        }
    }
}

__global__ __launch_bounds__(256, 2) void gemm_qkv(const float* __restrict__ bq,
                                                   const float* __restrict__ bkv)
{
    const int z = blockIdx.z;
    const __half* A = (z == 0) ? g_xq : (z == 1) ? g_xk : g_xv;
    const __half* B = (z == 0) ? g_wq : g_wk;
    const float* bias = (z == 0) ? bq : bkv;
    __half* C = (z == 0) ? g_q : (z == 1) ? g_k : g_v;
    gemm_body<true>(A, B, bias, nullptr, C);
}

__global__ __launch_bounds__(256, 2) void gemm_out(const float* __restrict__ bo,
                                                   float* __restrict__ out)
{
    gemm_body<false>(g_xo, g_wo, bo, out, nullptr);
}

// ============================================================================
// HMMA fused per-patch attention — round-13 structure with parallel softmax
// (8 warps x 6 rows, 16-lane shuffle reductions) fused with the P hi/lo
// fp16 conversion (deletes the separate convert pass + one barrier).
// ============================================================================
__global__ __launch_bounds__(256) void attn_kernel()
{
    extern __shared__ __align__(16) char smraw[];
    const uint32_t sm = smem_u32(smraw);
    const uint32_t qs = sm + QS_OFF, ks = sm + KS_OFF, vs = sm + VS_OFF;
    float* Sf = (float*)(smraw + SF_OFF);
    __half* Phc = (__half*)(smraw + PH_OFF);
    __half* Plc = (__half*)(smraw + PL_OFF);
    const uint32_t phA = sm + PH_OFF, plA = sm + PL_OFF;

    const int patch = blockIdx.x;
    const size_t base = (size_t)patch * L * D;
    const int tid = threadIdx.x;
    const int wid = tid >> 5, lane = tid & 31;
    const int mb = wid & 3;
    const int gr = lane >> 2, tc = lane & 3;

    const uint32_t aRowOff = (uint32_t)(mb * 16 + (lane & 15)) * QROWB;
    const uint32_t aOff = (uint32_t)(((lane >> 4) & 1) * 16);
    const uint32_t bRowBase = (uint32_t)(((lane >> 4) & 1) * 8 + (lane & 7));
    const uint32_t bOff = (uint32_t)(((lane >> 3) & 1) * 16);
    const int ng0 = (wid < 4) ? 0 : 1;
    const int ntiles = (wid < 4) ? 2 : 1;

    float accS[2][2][4];
#pragma unroll
    for (int t = 0; t < 2; t++)
#pragma unroll
        for (int j = 0; j < 2; j++)
#pragma unroll
            for (int e = 0; e < 4; e++) accS[t][j][e] = 0.0f;

    auto load_half = [&](int h) {
        const uint32_t p = (uint32_t)(h & 1) * 128;
        const int d0 = h * 64;
#pragma unroll
        for (int r = 0; r < 3; r++) {
            int id = tid + r * 256;          // 0..767
            int isK = id >= 384;
            int li = isK ? id - 384 : id;    // 0..383
            int rw = li >> 3, g = li & 7;
            uint32_t dst = (isK ? ks : qs) + rw * QROWB + p + g * 16;
            const __half* src = (isK ? g_k : g_q) + base + (size_t)rw * D + d0 + g * 8;
            cp_async16(dst, src);
        }
        cp_commit();
    };

    // ---- Stage 1: S = q k^T, 8 half-chunks of 64 cols, double-buffered ----
    load_half(0);
    for (int h = 0; h < 8; h++) {
        cp_wait<0>();
        __syncthreads();
        if (h + 1 < 8) load_half(h + 1);

        const uint32_t p = (uint32_t)(h & 1) * 128;
#pragma unroll
        for (int kk = 0; kk < 4; kk++) {
            uint32_t a[4];
            ldsm4(a, qs + aRowOff + p + kk * 32 + aOff);
#pragma unroll
            for (int t = 0; t < 2; t++) {
                if (t >= ntiles) break;
                int ng = ng0 + t * 2;
                uint32_t b[4];
                ldsm4(b, ks + (uint32_t)(ng * 16) * QROWB + bRowBase * QROWB + p + kk * 32 + bOff);
                mma16816(accS[t][0], a, &b[0]);
                mma16816(accS[t][1], a, &b[2]);
            }
        }
        __syncthreads();
    }

    // Prefetch v chunk 0 into vs — completes under S-store/softmax.
#pragma unroll
    for (int r = 0; r < 3; r++) {
        int id = tid + r * 256;
        int rw = id >> 4, g = id & 15;
        cp_async16(vs + rw * QROWB + g * 16, g_v + base + (size_t)rw * D + g * 8);
    }
    cp_commit();

    // store S (band 3 discarded)
    if (mb < 3) {
#pragma unroll
        for (int t = 0; t < 2; t++) {
            if (t >= ntiles) break;
            int ng = ng0 + t * 2;
#pragma unroll
            for (int j = 0; j < 2; j++) {
                int col = ng * 16 + j * 8 + tc * 2;
                Sf[(mb * 16 + gr) * 49 + col]         = accS[t][j][0];
                Sf[(mb * 16 + gr) * 49 + col + 1]     = accS[t][j][1];
                Sf[(mb * 16 + gr + 8) * 49 + col]     = accS[t][j][2];
                Sf[(mb * 16 + gr + 8) * 49 + col + 1] = accS[t][j][3];
            }
        }
    }
    __syncthreads();

    // ---- Stage 2: parallel softmax (8 warps x 6 rows; 16-lane groups,
    //      3 cols/lane) fused with P hi/lo fp16 conversion.
    //      Lanes 16-31 duplicate lanes 0-15 (benign same-value writes).
    {
        const float scale = 0.044194173824159216f;   // 512^-0.5
        const int ln16 = lane & 15;
        const int c0 = ln16 * 3;
#pragma unroll
        for (int rr = 0; rr < 6; rr++) {
            const int row = wid * 6 + rr;
            float x0 = Sf[row * 49 + c0] * scale;
            float x1 = Sf[row * 49 + c0 + 1] * scale;
            float x2 = Sf[row * 49 + c0 + 2] * scale;
            if (c0 == row)     x0 = -INFINITY;
            if (c0 + 1 == row) x1 = -INFINITY;
            if (c0 + 2 == row) x2 = -INFINITY;
            float m = fmaxf(x0, fmaxf(x1, x2));
#pragma unroll
            for (int off = 8; off; off >>= 1)
                m = fmaxf(m, __shfl_xor_sync(0xFFFFFFFFu, m, off, 16));
            float e0 = __expf(x0 - m);
            float e1 = __expf(x1 - m);
            float e2 = __expf(x2 - m);
            float s = e0 + e1 + e2;
#pragma unroll
            for (int off = 8; off; off >>= 1)
                s += __shfl_xor_sync(0xFFFFFFFFu, s, off, 16);
            float inv = 1.0f / s;
            float p3[3] = {e0 * inv, e1 * inv, e2 * inv};
#pragma unroll
            for (int j = 0; j < 3; j++) {
                __half hh = __float2half(p3[j]);
                Phc[row * (P_ROWB / 2) + c0 + j] = hh;
                Plc[row * (P_ROWB / 2) + c0 + j] =
                    __float2half(p3[j] - __half2float(hh));
            }
        }
    }

    // ---- Stage 3: out = P @ v, 4 chunks of 128 d-cols, ping-pong vs/qs ----
    const int qd = lane >> 3;
    const uint32_t vRow = (uint32_t)((qd & 1) * 8 + (lane & 7));
    const uint32_t vCol = (uint32_t)(wid * 32 + (qd >> 1) * 16);
    const uint32_t pRow = (uint32_t)(lane & 15);

    for (int cc = 0; cc < 4; cc++) {
        const int d0 = cc * 128;
        cp_wait<0>();
        __syncthreads();                     // chunk cc + P conversion visible
        if (cc + 1 < 4) {
            const uint32_t nb = ((cc + 1) & 1) ? qs : vs;
            const int nd0 = (cc + 1) * 128;
#pragma unroll
            for (int r = 0; r < 3; r++) {
                int id = tid + r * 256;
                int rw = id >> 4, g = id & 15;
                cp_async16(nb + rw * QROWB + g * 16,
                           g_v + base + (size_t)rw * D + nd0 + g * 8);
            }
            cp_commit();
        }
        const uint32_t vb = (cc & 1) ? qs : vs;

        float acc[3][2][4];
#pragma unroll
        for (int i = 0; i < 3; i++)
#pragma unroll
            for (int j = 0; j < 2; j++)
#pragma unroll
                for (int e = 0; e < 4; e++) acc[i][j][e] = 0.0f;

#pragma unroll
        for (int kk = 0; kk < 3; kk++) {
            uint32_t b[4];
            ldsm4t(b, vb + (uint32_t)(kk * 16 + vRow) * QROWB + vCol);
#pragma unroll
            for (int mbb = 0; mbb < 3; mbb++) {
                uint32_t ah[4], al[4];
                ldsm4(ah, phA + (uint32_t)(mbb * 16 + pRow) * P_ROWB + kk * 32 + aOff);
                ldsm4(al, plA + (uint32_t)(mbb * 16 + pRow) * P_ROWB + kk * 32 + aOff);
                mma16816(acc[mbb][0], ah, &b[0]);
                mma16816(acc[mbb][1], ah, &b[2]);
                mma16816(acc[mbb][0], al, &b[0]);
                mma16816(acc[mbb][1], al, &b[2]);
            }
        }

#pragma unroll
        for (int mbb = 0; mbb < 3; mbb++)
#pragma unroll
            for (int j = 0; j < 2; j++) {
                int row = mbb * 16 + gr;
                int col = d0 + wid * 16 + j * 8 + tc * 2;
                __half2 p0, p1;
                p0.x = __float2half(acc[mbb][j][0]);
                p0.y = __float2half(acc[mbb][j][1]);
                p1.x = __float2half(acc[mbb][j][2]);
                p1.y = __float2half(acc[mbb][j][3]);
                *(__half2*)(g_xo + base + (size_t)row * D + col) = p0;
                *(__half2*)(g_xo + base + (size_t)(row + 8) * D + col) = p1;
            }
        __syncthreads();                     // done reading vb before overwrite
    }
}

// ============================================================================
extern "C" void kernel_launch(void* const* d_in, const int* in_sizes, int n_in,
                              void* d_out, int out_size)
{
    const float* queries = (const float*)d_in[0];
    const float* keys    = (const float*)d_in[1];
    const float* values  = (const float*)d_in[2];
    const float* Wq      = (const float*)d_in[3];
    const float* bq      = (const float*)d_in[4];
    const float* Wkv     = (const float*)d_in[5];
    const float* bkv     = (const float*)d_in[6];
    const float* Wo      = (const float*)d_in[7];
    const float* bo      = (const float*)d_in[8];
    float* out = (float*)d_out;

    cudaFuncSetAttribute(gemm_qkv, cudaFuncAttributeMaxDynamicSharedMemorySize,
                         SMEM_DYN);
    cudaFuncSetAttribute(gemm_out, cudaFuncAttributeMaxDynamicSharedMemorySize,
                         SMEM_DYN);
    cudaFuncSetAttribute(attn_kernel, cudaFuncAttributeMaxDynamicSharedMemorySize,
                         ATTN_SMEM);

    conv_inputs<<<(int)(((size_t)MTOT * D / 8) / 256), 256>>>(queries, keys, values);
    conv_weights<<<(D * D / 8) / 256, 256>>>(Wq, Wkv, Wo);

    dim3 gqkv(D / BN, MTOT / BM, 3);
    gemm_qkv<<<gqkv, 256, SMEM_DYN>>>(bq, bkv);

    attn_kernel<<<NPATCH, 256, ATTN_SMEM>>>();

    dim3 gout(D / BN, MTOT / BM);
    gemm_out<<<gout, 256, SMEM_DYN>>>(bo, out);
}

// round 17
// speedup vs baseline: 1.0242x; 1.0018x over previous
#include <cuda_runtime.h>
#include <cuda_fp16.h>
#include <math.h>
#include <stdint.h>

// ============================================================================
// Problem constants
// ============================================================================
namespace {
constexpr int D = 512;
constexpr int L = 48;
constexpr int NPATCH = 8 * 7 * 24;     // 1344
constexpr int MTOT = NPATCH * L;       // 64512
constexpr int BM = 128, BN = 128;
constexpr int BK = 64;                 // fp16 elems per chunk
constexpr int NK0 = D / BK;            // 8 chunks
constexpr int NS = 3;                  // pipeline stages
constexpr int ROWB = 144;              // 128 data bytes + 16 pad (9 granules)
constexpr int ATILEB = 128 * ROWB;     // 18432
constexpr int STAGEB = 2 * ATILEB;     // 36864 (A + B)
constexpr int SMEM_DYN = NS * STAGEB;  // 110592  -> 2 CTAs/SM

constexpr int GEMM_CTAS = (D / BN) * (MTOT / BM);        // 2016
constexpr size_t CONV_U4 = (size_t)MTOT * D / 8;         // 4128768 uint4 tasks
constexpr int QCONV_BLKS = (int)(CONV_U4 / 256);          // 16128
constexpr int WCONV_BLKS = (D * D / 8) / 256;             // 128

// attention smem layout (bytes)
constexpr int QROWB = 272;             // 128 fp16 data + 16B pad (17 granules)
constexpr int QS_B = 64 * QROWB;       // (rows 48-63 unused)
constexpr int KS_B = 48 * QROWB;
constexpr int VS_B = 48 * QROWB;
constexpr int SF_B = 48 * 49 * 4;
constexpr int P_ROWB = 112;            // 48 fp16 + 16B pad (7 granules)
constexpr int PH_B = 48 * P_ROWB;
constexpr int QS_OFF = 0;
constexpr int KS_OFF = QS_OFF + QS_B;
constexpr int VS_OFF = KS_OFF + KS_B;
constexpr int SF_OFF = VS_OFF + VS_B;
constexpr int PH_OFF = SF_OFF + SF_B;
constexpr int PL_OFF = PH_OFF + PH_B;
constexpr int ATTN_SMEM = PL_OFF + PH_B;   // 63680
}

// ============================================================================
// Scratch (__device__ globals; no cudaMalloc allowed)
// ============================================================================
__device__ __half g_xq[(size_t)MTOT * D];   // inputs rounded to fp16
__device__ __half g_xk[(size_t)MTOT * D];
__device__ __half g_xv[(size_t)MTOT * D];
__device__ __half g_q[(size_t)MTOT * D];    // projections (fp16)
__device__ __half g_k[(size_t)MTOT * D];
__device__ __half g_v[(size_t)MTOT * D];
__device__ __half g_xo[(size_t)MTOT * D];   // attention out, fp16
__device__ __half g_wq[D * D];              // weights rounded to fp16
__device__ __half g_wk[D * D];
__device__ __half g_wo[D * D];

// ============================================================================
// PTX helpers (sm_90-compatible baseline PTX only — NO tcgen05; harness
// compiles PTX for compute_103 without the 'a' suffix)
// ============================================================================
__device__ __forceinline__ uint32_t smem_u32(const void* p) {
    uint32_t a;
    asm("{ .reg .u64 t; cvta.to.shared.u64 t, %1; cvt.u32.u64 %0, t; }"
        : "=r"(a) : "l"(p));
    return a;
}
__device__ __forceinline__ void cp_async16(uint32_t dst, const void* src) {
    asm volatile("cp.async.cg.shared.global [%0], [%1], 16;" :: "r"(dst), "l"(src));
}
__device__ __forceinline__ void cp_commit() {
    asm volatile("cp.async.commit_group;" ::: "memory");
}
template <int N>
__device__ __forceinline__ void cp_wait() {
    asm volatile("cp.async.wait_group %0;" :: "n"(N) : "memory");
}
__device__ __forceinline__ void ldsm4(uint32_t* r, uint32_t addr) {
    asm volatile("ldmatrix.sync.aligned.m8n8.x4.shared.b16 {%0,%1,%2,%3}, [%4];"
                 : "=r"(r[0]), "=r"(r[1]), "=r"(r[2]), "=r"(r[3]) : "r"(addr));
}
__device__ __forceinline__ void ldsm4t(uint32_t* r, uint32_t addr) {
    asm volatile("ldmatrix.sync.aligned.m8n8.x4.trans.shared.b16 {%0,%1,%2,%3}, [%4];"
                 : "=r"(r[0]), "=r"(r[1]), "=r"(r[2]), "=r"(r[3]) : "r"(addr));
}
__device__ __forceinline__ void mma16816(float* c, const uint32_t* a,
                                         const uint32_t* b) {
    asm volatile(
        "mma.sync.aligned.m16n8k16.row.col.f32.f16.f16.f32 "
        "{%0,%1,%2,%3}, {%4,%5,%6,%7}, {%8,%9}, {%0,%1,%2,%3};"
        : "+f"(c[0]), "+f"(c[1]), "+f"(c[2]), "+f"(c[3])
        : "r"(a[0]), "r"(a[1]), "r"(a[2]), "r"(a[3]), "r"(b[0]), "r"(b[1]));
}

// ============================================================================
// conversions
// ============================================================================
__device__ __forceinline__ uint32_t pack_h2(float a, float b) {
    __half2 h = __floats2half2_rn(a, b);
    return *(uint32_t*)&h;
}
__device__ __forceinline__ void conv_u4(const float* __restrict__ src,
                                        __half* __restrict__ dst, size_t i8) {
    float4 a0 = ((const float4*)src)[i8 * 2];
    float4 a1 = ((const float4*)src)[i8 * 2 + 1];
    *(uint4*)(dst + i8 * 8) = make_uint4(pack_h2(a0.x, a0.y), pack_h2(a0.z, a0.w),
                                         pack_h2(a1.x, a1.y), pack_h2(a1.z, a1.w));
}

// q conversion + all weights (one launch)
__global__ __launch_bounds__(256) void conv_q_w(
    const float* __restrict__ q, const float* __restrict__ wq,
    const float* __restrict__ wkv, const float* __restrict__ wo)
{
    int b = blockIdx.x;
    if (b < QCONV_BLKS) {
        conv_u4(q, g_xq, (size_t)b * 256 + threadIdx.x);
    } else {
        size_t i8 = (size_t)(b - QCONV_BLKS) * 256 + threadIdx.x;
        conv_u4(wq, g_wq, i8);
        conv_u4(wkv, g_wk, i8);
        conv_u4(wo, g_wo, i8);
    }
}

// ============================================================================
// HMMA GEMM (fp16 1-term): C[m][n] = sum_d A[m][d]*W[n][d] + bias[n]
// BM=128 x BN=128 x BK=64, 256 threads (2x4 warp grid, 64x32 per warp),
// NS=3 pipeline, ONE __syncthreads per chunk, 2 CTAs/SM.   (round-9 proven)
// Optional epilogue: grid-strided fp32->fp16 conversion of the NEXT GEMM's
// A tensor (after acc regs are dead; race-free across launch boundaries).
// convDst is selected IN DEVICE CODE (taking the address of a __device__
// symbol in host code yields the host shadow — the round-16 bug).
// ============================================================================
template <bool WriteHalf>
__device__ __forceinline__ void gemm_body(
    const __half* __restrict__ A, const __half* __restrict__ B,
    const float* __restrict__ bias, float* __restrict__ Cf,
    __half* __restrict__ Ch,
    const float* __restrict__ convSrc, __half* __restrict__ convDst)
{
    extern __shared__ __align__(16) char dsm[];
    const uint32_t smem = smem_u32(dsm);
    __shared__ float bias_s[BN];

    const int tid = threadIdx.x;
    const int wid = tid >> 5, lane = tid & 31;
    const int wm = wid & 1, wn = wid >> 1;           // 2 x 4 warp grid
    const int n0 = blockIdx.x * BN;
    const int m0 = blockIdx.y * BM;

    if (tid < BN) bias_s[tid] = bias[n0 + tid];

    float acc[4][4][4];
#pragma unroll
    for (int i = 0; i < 4; i++)
#pragma unroll
        for (int j = 0; j < 4; j++)
#pragma unroll
            for (int e = 0; e < 4; e++) acc[i][j][e] = 0.0f;

    auto load_chunk = [&](int c) {
        const int s = c % NS;
        const int k0 = c * BK;
        const uint32_t st = smem + (uint32_t)s * STAGEB;
#pragma unroll
        for (int r = 0; r < 4; r++) {
            int id = tid + r * 256;          // 0..1023
            int row = id >> 3, g = id & 7;
            cp_async16(st + row * ROWB + g * 16,
                       A + (size_t)(m0 + row) * D + k0 + g * 8);
            cp_async16(st + ATILEB + row * ROWB + g * 16,
                       B + (size_t)(n0 + row) * D + k0 + g * 8);
        }
        cp_commit();
    };

    load_chunk(0);
    load_chunk(1);

    const uint32_t aLaneRow = (uint32_t)(wm * 64 + (lane & 15));
    const uint32_t aLaneOff = (uint32_t)(((lane >> 4) & 1) * 16);
    const uint32_t bLaneRow = (uint32_t)(wn * 32 + ((lane >> 4) & 1) * 8 + (lane & 7));
    const uint32_t bLaneOff = (uint32_t)(((lane >> 3) & 1) * 16);

    for (int c = 0; c < NK0; c++) {
        if (c == NK0 - 1) cp_wait<0>();
        else cp_wait<1>();
        __syncthreads();                     // all warps done reading buf (c-1)%NS
        if (c + NS - 1 < NK0) load_chunk(c + NS - 1);   // writes buf (c-1)%NS

        const int s = c % NS;
        const uint32_t st = smem + (uint32_t)s * STAGEB;
        const uint32_t aAddr = st + aLaneRow * ROWB + aLaneOff;
        const uint32_t bAddr = st + ATILEB + bLaneRow * ROWB + bLaneOff;

#pragma unroll
        for (int ks = 0; ks < 4; ks++) {
            uint32_t a[4][4], b[2][4];
#pragma unroll
            for (int mf = 0; mf < 4; mf++)
                ldsm4(a[mf], aAddr + mf * 16 * ROWB + ks * 32);
#pragma unroll
            for (int bp = 0; bp < 2; bp++)
                ldsm4(b[bp], bAddr + bp * 16 * ROWB + ks * 32);
#pragma unroll
            for (int mf = 0; mf < 4; mf++)
#pragma unroll
                for (int nf = 0; nf < 4; nf++)
                    mma16816(acc[mf][nf], a[mf], &b[nf >> 1][(nf & 1) * 2]);
        }
    }

    // Epilogue: C stores
    const int gr = lane >> 2, tc = lane & 3;
#pragma unroll
    for (int mf = 0; mf < 4; mf++) {
#pragma unroll
        for (int nf = 0; nf < 4; nf++) {
            int rowo = m0 + wm * 64 + mf * 16 + gr;
            int coll = wn * 32 + nf * 8 + tc * 2;
            int col = n0 + coll;
            float b0 = bias_s[coll], b1 = bias_s[coll + 1];
            float v0 = acc[mf][nf][0] + b0, v1 = acc[mf][nf][1] + b1;
            float v2 = acc[mf][nf][2] + b0, v3 = acc[mf][nf][3] + b1;
            if (WriteHalf) {
                __half2 p0; p0.x = __float2half(v0); p0.y = __float2half(v1);
                __half2 p1; p1.x = __float2half(v2); p1.y = __float2half(v3);
                *(__half2*)(Ch + (size_t)rowo * D + col) = p0;
                *(__half2*)(Ch + (size_t)(rowo + 8) * D + col) = p1;
            } else {
                float2 p0; p0.x = v0; p0.y = v1;
                float2 p1; p1.x = v2; p1.y = v3;
                *(float2*)(Cf + (size_t)rowo * D + col) = p0;
                *(float2*)(Cf + (size_t)(rowo + 8) * D + col) = p1;
            }
        }
    }

    // Epilogue: overlapped conversion slice (DRAM work under tensor-bound kernel)
    if (convSrc != nullptr) {
        const size_t stride = (size_t)GEMM_CTAS * 256;
        size_t i8 = ((size_t)blockIdx.y * gridDim.x + blockIdx.x) * 256 + tid;
        for (; i8 < CONV_U4; i8 += stride)
            conv_u4(convSrc, convDst, i8);
    }
}

__global__ __launch_bounds__(256, 2) void gemm_proj(
    int z, const float* __restrict__ bias, const float* __restrict__ convSrc)
{
    const __half* A = (z == 0) ? g_xq : (z == 1) ? g_xk : g_xv;
    const __half* B = (z == 0) ? g_wq : g_wk;
    __half* C = (z == 0) ? g_q : (z == 1) ? g_k : g_v;
    // device-side symbol resolution (host-side &g_xk is the shadow symbol!)
    __half* convDst = (z == 0) ? g_xk : g_xv;
    gemm_body<true>(A, B, bias, nullptr, C, convSrc, convDst);
}

__global__ __launch_bounds__(256, 2) void gemm_out(const float* __restrict__ bo,
                                                   float* __restrict__ out)
{
    gemm_body<false>(g_xo, g_wo, bo, out, nullptr, nullptr, nullptr);
}

// ============================================================================
// HMMA fused per-patch attention (round-15 proven; unchanged).
// ============================================================================
__global__ __launch_bounds__(256) void attn_kernel()
{
    extern __shared__ __align__(16) char smraw[];
    const uint32_t sm = smem_u32(smraw);
    const uint32_t qs = sm + QS_OFF, ks = sm + KS_OFF, vs = sm + VS_OFF;
    float* Sf = (float*)(smraw + SF_OFF);
    __half* Phc = (__half*)(smraw + PH_OFF);
    __half* Plc = (__half*)(smraw + PL_OFF);
    const uint32_t phA = sm + PH_OFF, plA = sm + PL_OFF;

    const int patch = blockIdx.x;
    const size_t base = (size_t)patch * L * D;
    const int tid = threadIdx.x;
    const int wid = tid >> 5, lane = tid & 31;
    const int mb = wid & 3;
    const int gr = lane >> 2, tc = lane & 3;

    const uint32_t aRowOff = (uint32_t)(mb * 16 + (lane & 15)) * QROWB;
    const uint32_t aOff = (uint32_t)(((lane >> 4) & 1) * 16);
    const uint32_t bRowBase = (uint32_t)(((lane >> 4) & 1) * 8 + (lane & 7));
    const uint32_t bOff = (uint32_t)(((lane >> 3) & 1) * 16);
    const int ng0 = (wid < 4) ? 0 : 1;
    const int ntiles = (wid < 4) ? 2 : 1;

    float accS[2][2][4];
#pragma unroll
    for (int t = 0; t < 2; t++)
#pragma unroll
        for (int j = 0; j < 2; j++)
#pragma unroll
            for (int e = 0; e < 4; e++) accS[t][j][e] = 0.0f;

    auto load_half = [&](int h) {
        const uint32_t p = (uint32_t)(h & 1) * 128;
        const int d0 = h * 64;
#pragma unroll
        for (int r = 0; r < 3; r++) {
            int id = tid + r * 256;          // 0..767
            int isK = id >= 384;
            int li = isK ? id - 384 : id;    // 0..383
            int rw = li >> 3, g = li & 7;
            uint32_t dst = (isK ? ks : qs) + rw * QROWB + p + g * 16;
            const __half* src = (isK ? g_k : g_q) + base + (size_t)rw * D + d0 + g * 8;
            cp_async16(dst, src);
        }
        cp_commit();
    };

    // ---- Stage 1: S = q k^T, 8 half-chunks of 64 cols, double-buffered ----
    load_half(0);
    for (int h = 0; h < 8; h++) {
        cp_wait<0>();
        __syncthreads();
        if (h + 1 < 8) load_half(h + 1);

        const uint32_t p = (uint32_t)(h & 1) * 128;
#pragma unroll
        for (int kk = 0; kk < 4; kk++) {
            uint32_t a[4];
            ldsm4(a, qs + aRowOff + p + kk * 32 + aOff);
#pragma unroll
            for (int t = 0; t < 2; t++) {
                if (t >= ntiles) break;
                int ng = ng0 + t * 2;
                uint32_t b[4];
                ldsm4(b, ks + (uint32_t)(ng * 16) * QROWB + bRowBase * QROWB + p + kk * 32 + bOff);
                mma16816(accS[t][0], a, &b[0]);
                mma16816(accS[t][1], a, &b[2]);
            }
        }
        __syncthreads();
    }

    // Prefetch v chunk 0 into vs — completes under S-store/softmax.
#pragma unroll
    for (int r = 0; r < 3; r++) {
        int id = tid + r * 256;
        int rw = id >> 4, g = id & 15;
        cp_async16(vs + rw * QROWB + g * 16, g_v + base + (size_t)rw * D + g * 8);
    }
    cp_commit();

    // store S (band 3 discarded)
    if (mb < 3) {
#pragma unroll
        for (int t = 0; t < 2; t++) {
            if (t >= ntiles) break;
            int ng = ng0 + t * 2;
#pragma unroll
            for (int j = 0; j < 2; j++) {
                int col = ng * 16 + j * 8 + tc * 2;
                Sf[(mb * 16 + gr) * 49 + col]         = accS[t][j][0];
                Sf[(mb * 16 + gr) * 49 + col + 1]     = accS[t][j][1];
                Sf[(mb * 16 + gr + 8) * 49 + col]     = accS[t][j][2];
                Sf[(mb * 16 + gr + 8) * 49 + col + 1] = accS[t][j][3];
            }
        }
    }
    __syncthreads();

    // ---- Stage 2: parallel softmax fused with P hi/lo fp16 conversion ----
    {
        const float scale = 0.044194173824159216f;   // 512^-0.5
        const int ln16 = lane & 15;
        const int c0 = ln16 * 3;
#pragma unroll
        for (int rr = 0; rr < 6; rr++) {
            const int row = wid * 6 + rr;
            float x0 = Sf[row * 49 + c0] * scale;
            float x1 = Sf[row * 49 + c0 + 1] * scale;
            float x2 = Sf[row * 49 + c0 + 2] * scale;
            if (c0 == row)     x0 = -INFINITY;
            if (c0 + 1 == row) x1 = -INFINITY;
            if (c0 + 2 == row) x2 = -INFINITY;
            float m = fmaxf(x0, fmaxf(x1, x2));
#pragma unroll
            for (int off = 8; off; off >>= 1)
                m = fmaxf(m, __shfl_xor_sync(0xFFFFFFFFu, m, off, 16));
            float e0 = __expf(x0 - m);
            float e1 = __expf(x1 - m);
            float e2 = __expf(x2 - m);
            float s = e0 + e1 + e2;
#pragma unroll
            for (int off = 8; off; off >>= 1)
                s += __shfl_xor_sync(0xFFFFFFFFu, s, off, 16);
            float inv = 1.0f / s;
            float p3[3] = {e0 * inv, e1 * inv, e2 * inv};
#pragma unroll
            for (int j = 0; j < 3; j++) {
                __half hh = __float2half(p3[j]);
                Phc[row * (P_ROWB / 2) + c0 + j] = hh;
                Plc[row * (P_ROWB / 2) + c0 + j] =
                    __float2half(p3[j] - __half2float(hh));
            }
        }
    }

    // ---- Stage 3: out = P @ v, 4 chunks of 128 d-cols, ping-pong vs/qs ----
    const int qd = lane >> 3;
    const uint32_t vRow = (uint32_t)((qd & 1) * 8 + (lane & 7));
    const uint32_t vCol = (uint32_t)(wid * 32 + (qd >> 1) * 16);
    const uint32_t pRow = (uint32_t)(lane & 15);

    for (int cc = 0; cc < 4; cc++) {
        const int d0 = cc * 128;
        cp_wait<0>();
        __syncthreads();                     // chunk cc + P conversion visible
        if (cc + 1 < 4) {
            const uint32_t nb = ((cc + 1) & 1) ? qs : vs;
            const int nd0 = (cc + 1) * 128;
#pragma unroll
            for (int r = 0; r < 3; r++) {
                int id = tid + r * 256;
                int rw = id >> 4, g = id & 15;
                cp_async16(nb + rw * QROWB + g * 16,
                           g_v + base + (size_t)rw * D + nd0 + g * 8);
            }
            cp_commit();
        }
        const uint32_t vb = (cc & 1) ? qs : vs;

        float acc[3][2][4];
#pragma unroll
        for (int i = 0; i < 3; i++)
#pragma unroll
            for (int j = 0; j < 2; j++)
#pragma unroll
                for (int e = 0; e < 4; e++) acc[i][j][e] = 0.0f;

#pragma unroll
        for (int kk = 0; kk < 3; kk++) {
            uint32_t b[4];
            ldsm4t(b, vb + (uint32_t)(kk * 16 + vRow) * QROWB + vCol);
#pragma unroll
            for (int mbb = 0; mbb < 3; mbb++) {
                uint32_t ah[4], al[4];
                ldsm4(ah, phA + (uint32_t)(mbb * 16 + pRow) * P_ROWB + kk * 32 + aOff);
                ldsm4(al, plA + (uint32_t)(mbb * 16 + pRow) * P_ROWB + kk * 32 + aOff);
                mma16816(acc[mbb][0], ah, &b[0]);
                mma16816(acc[mbb][1], ah, &b[2]);
                mma16816(acc[mbb][0], al, &b[0]);
                mma16816(acc[mbb][1], al, &b[2]);
            }
        }

#pragma unroll
        for (int mbb = 0; mbb < 3; mbb++)
#pragma unroll
            for (int j = 0; j < 2; j++) {
                int row = mbb * 16 + gr;
                int col = d0 + wid * 16 + j * 8 + tc * 2;
                __half2 p0, p1;
                p0.x = __float2half(acc[mbb][j][0]);
                p0.y = __float2half(acc[mbb][j][1]);
                p1.x = __float2half(acc[mbb][j][2]);
                p1.y = __float2half(acc[mbb][j][3]);
                *(__half2*)(g_xo + base + (size_t)row * D + col) = p0;
                *(__half2*)(g_xo + base + (size_t)(row + 8) * D + col) = p1;
            }
        __syncthreads();
    }
}

// ============================================================================
// Launch: conv_q+w -> gemm_q(+conv k) -> gemm_k(+conv v) -> gemm_v
//         -> attn -> gemm_out.  Conversions of k/v ride the tensor-bound
//         GEMM epilogues (register-dead region; kernel-boundary ordering).
// ============================================================================
extern "C" void kernel_launch(void* const* d_in, const int* in_sizes, int n_in,
                              void* d_out, int out_size)
{
    const float* queries = (const float*)d_in[0];
    const float* keys    = (const float*)d_in[1];
    const float* values  = (const float*)d_in[2];
    const float* Wq      = (const float*)d_in[3];
    const float* bq      = (const float*)d_in[4];
    const float* Wkv     = (const float*)d_in[5];
    const float* bkv     = (const float*)d_in[6];
    const float* Wo      = (const float*)d_in[7];
    const float* bo      = (const float*)d_in[8];
    float* out = (float*)d_out;

    cudaFuncSetAttribute(gemm_proj, cudaFuncAttributeMaxDynamicSharedMemorySize,
                         SMEM_DYN);
    cudaFuncSetAttribute(gemm_out, cudaFuncAttributeMaxDynamicSharedMemorySize,
                         SMEM_DYN);
    cudaFuncSetAttribute(attn_kernel, cudaFuncAttributeMaxDynamicSharedMemorySize,
                         ATTN_SMEM);

    conv_q_w<<<QCONV_BLKS + WCONV_BLKS, 256>>>(queries, Wq, Wkv, Wo);

    const dim3 gproj(D / BN, MTOT / BM);
    gemm_proj<<<gproj, 256, SMEM_DYN>>>(0, bq, keys);     // + convert k -> g_xk
    gemm_proj<<<gproj, 256, SMEM_DYN>>>(1, bkv, values);  // + convert v -> g_xv
    gemm_proj<<<gproj, 256, SMEM_DYN>>>(2, bkv, nullptr);

    attn_kernel<<<NPATCH, 256, ATTN_SMEM>>>();

    gemm_out<<<gproj, 256, SMEM_DYN>>>(bo, out);
}